// round 15
// baseline (speedup 1.0000x reference)
#include <cuda_runtime.h>
#include <cstdint>
#include <math.h>

#define NIMG     8
#define GH       128
#define GW       128
#define NA       9
#define NANCH    (GH*GW*NA)      /* 147456 */
#define NC       86
#define CAPF     512             /* candidate capacity */
#define CAP      2048            /* full-fallback cap */
#define PRE_T    3.0f            /* expected count ~199 +/- 14; [128,256] at -5/+4 sigma */
#define MINC     128
#define MAXC     256             /* fast path upper bound (sort width) */
#define TOPK     1000
#define MAXDET   100
#define SCORE_TH 0.5f
#define IOU_TH   0.75f
#define NMSW     128             /* IoU bit-matrix window */
#define NT       512             /* block size */
#define K1T      512             /* prefilter threads */
#define K1PER    16              /* anchors per prefilter thread (front-batched MLP=16) */
#define K1B      (NANCH / (K1T * K1PER))   /* 18 blocks/image -> 144 CTAs = ONE wave */

typedef unsigned long long u64;
typedef unsigned int       u32;

__device__ u64 g_buf[NIMG][CAPF];
__device__ __align__(16) float g_rec[NIMG][CAPF][8];  /* di,dj,dh,dw,score,label,-,- */
__device__ int g_cnt[NIMG];

static __device__ __forceinline__ u64 pack_key(float s, int n) {
    // s >= 0.5 > 0 -> orderable bits = bits|sign. DESCENDING sort; low word = ~n
    // gives "smaller index first" on ties (lax.top_k semantics).
    u32 sb = __float_as_uint(s) | 0x80000000u;
    return ((u64)sb << 32) | (u32)(~n);
}

// ===================== K1: single-wave prefilter (DRAM-floor scan) + per-hit records =====================
__global__ __launch_bounds__(K1T, 1)
void prefilter_kernel(const float* __restrict__ in) {
    __shared__ uint4 hitlist[CAPF];   // appends gated by slot<CAPF => no overflow
    __shared__ int s_hc;

    const int img = blockIdx.y;
    const int tid = threadIdx.x;
    const float* ibase = in + (size_t)img * NANCH * NC;

    if (tid == 0) s_hc = 0;
    __syncthreads();

    // front-batched MLP=16 scan of this CTA's 8192-anchor slice
    const int base = blockIdx.x * (K1T * K1PER);
    float v[K1PER];
    #pragma unroll
    for (int k = 0; k < K1PER; k++)
        v[k] = __ldg(ibase + (size_t)(base + tid + k * K1T) * NC + 5);
    #pragma unroll
    for (int k = 0; k < K1PER; k++) {
        if (v[k] >= PRE_T) {
            int n = base + tid + k * K1T;
            int p = atomicAdd(&g_cnt[img], 1);
            if (p < CAPF) {
                g_buf[img][p] = pack_key(v[k], n);
                int h = atomicAdd(&s_hc, 1);
                hitlist[h] = make_uint4((u32)p, (u32)n, __float_as_uint(v[k]), 0u);
            }
        }
    }
    __syncthreads();

    // post-pass: one WARP per hit -> parallel class argmax + box decode -> g_rec
    const int hc = s_hc;                 // ~14 per CTA typically
    const int w = tid >> 5, lane = tid & 31;
    for (int h = w; h < hc; h += K1T / 32) {
        uint4 e = hitlist[h];
        const int n = (int)e.y;
        const float* row = ibase + (size_t)n * NC;
        float bv = __ldg(row + 6 + lane);
        int bidx = lane;
        float v1 = __ldg(row + 6 + 32 + lane);
        float v2 = (lane < 16) ? __ldg(row + 6 + 64 + lane) : -1e38f;
        if (v1 > bv) { bv = v1; bidx = 32 + lane; }
        if (v2 > bv) { bv = v2; bidx = 64 + lane; }
        #pragma unroll
        for (int off = 16; off; off >>= 1) {
            float ov = __shfl_down_sync(0xffffffffu, bv, off);
            int   oi = __shfl_down_sync(0xffffffffu, bidx, off);
            if (ov > bv || (ov == bv && oi < bidx)) { bv = ov; bidx = oi; }
        }
        if (lane == 0) {
            int a = n % NA;
            int cell = n / NA;
            int gj = cell % GW;
            int gi = cell / GW;
            int si = a / 3, ri = a % 3;
            float s  = 0.5f * (float)(1 << si);
            float r  = 0.5f * (float)(1 << ri);
            float sr = sqrtf(r);
            float ah = (s * sr) * 0.03125f;          // ANCHOR_BASE_CELLS / 128
            float aw = (s / sr) * 0.03125f;
            float ci = ((float)gi + 0.5f) * (1.0f / 128.0f);
            float cj = ((float)gj + 0.5f) * (1.0f / 128.0f);
            float2 t01 = *(const float2*)row;
            float2 t23 = *(const float2*)(row + 2);
            float di = ci + t01.x * ah;
            float dj = cj + t01.y * aw;
            float dh = ah * expf(t23.x);
            float dw = aw * expf(t23.y);
            float* rec = &g_rec[img][e.x][0];
            *(float4*)rec       = make_float4(di, dj, dh, dw);
            *(float2*)(rec + 4) = make_float2(__uint_as_float(e.z), (float)bidx);
        }
    }
}

// ===================== K2: front-batched head + register bitonic + NMS =====================
static __device__ __forceinline__ void shfl_cmp_kv(u64& k, u32& p, int j, bool desc, int lane) {
    u64 ok = __shfl_xor_sync(0xffffffffu, k, j);
    u32 op = __shfl_xor_sync(0xffffffffu, p, j);
    bool upper = (lane & j) == 0;                   // smaller-index position
    bool keep_max = (upper == desc);
    bool mine_max = k > ok;
    if (keep_max != mine_max) { k = ok; p = op; }
}

__global__ __launch_bounds__(NT, 1)
void topk_nms_kernel(const float* __restrict__ in, float* __restrict__ out) {
    __shared__ __align__(16) u64 keys[CAP];          // sorted keys; overlaid by cor[] after decode
    __shared__ u32  pay[CAPF];
    __shared__ __align__(16) float4 s_rec[MAXC * 2]; // smem copy of g_rec slots 0..255 (fast path)
    __shared__ __align__(16) float4 c_box[1024];
    __shared__ float c_score[1024];
    __shared__ float c_lab[1024];
    __shared__ int   c_idx[1024];                    // full-fallback only
    __shared__ __align__(16) u32 rowsw[NMSW + 1][4];
    __shared__ int   kept_rank[MAXDET];
    __shared__ int   s_nk;
    __shared__ int   s_fcnt;
    __shared__ int   s_flag;
    __shared__ u32   s_any;

    const int img = blockIdx.x;
    const int tid = threadIdx.x;
    const int w = tid >> 5, lane = tid & 31;
    const float* ibase = in + (size_t)img * NANCH * NC;
    float4* cor = (float4*)keys;

    // ---- front-batched head: ALL loads issued before any dependency on cnt ----
    u64 x = 0, y = 0; u32 xp = 0, yp = 0;
    if (w < 4) {
        // sort warps: load their g_buf slots unconditionally (fixed array, always valid)
        int i0 = 64 * w + lane;
        xp = i0; yp = i0 + 32;
        x = g_buf[img][i0];
        y = g_buf[img][i0 + 32];
    } else {
        // remaining 12 warps: stream g_rec slots 0..255 into smem unconditionally
        int t0 = tid - 128;
        const float4* src = (const float4*)&g_rec[img][0][0];
        #pragma unroll
        for (int r = 0; r < 2; r++) {
            int i = t0 + r * 384;
            if (i < MAXC * 2) s_rec[i] = src[i];
        }
    }
    int cnt = g_cnt[img];                // in flight concurrently with the above
    __syncthreads();
    if (tid == 0) g_cnt[img] = 0;        // reset for next replay (stream-ordered)

    bool full = !(cnt >= MINC && cnt <= MAXC);
    int M = 0;

    if (!full) {
        M = cnt;
        if (w < 4) {
            // mask padding AFTER cnt arrives (keys already in registers)
            int i0 = 64 * w + lane;
            if (i0 >= cnt)      x = 0ull;
            if (i0 + 32 >= cnt) y = 0ull;

            // ---- per-warp 64-element register bitonic sort (block w desc iff w even) ----
            const bool block_desc = ((w & 1) == 0);
            const bool flip = !block_desc;
            #pragma unroll
            for (int k = 2; k <= 16; k <<= 1)
                #pragma unroll
                for (int j = k >> 1; j; j >>= 1) {
                    bool d = (((lane & k) == 0) != flip);
                    shfl_cmp_kv(x, xp, j, d, lane);
                    shfl_cmp_kv(y, yp, j, d, lane);
                }
            { // k=32: halves opposite directions
                bool dx = !flip, dy = flip;
                #pragma unroll
                for (int j = 16; j; j >>= 1) { shfl_cmp_kv(x, xp, j, dx, lane); shfl_cmp_kv(y, yp, j, dy, lane); }
            }
            { // k=64
                bool d = block_desc;
                bool xmax = x > y;
                if (xmax != d) { u64 tk = x; x = y; y = tk; u32 tp = xp; xp = yp; yp = tp; }
                #pragma unroll
                for (int j = 16; j; j >>= 1) { shfl_cmp_kv(x, xp, j, d, lane); shfl_cmp_kv(y, yp, j, d, lane); }
            }
            keys[64 * w + lane] = x;        pay[64 * w + lane] = xp;
            keys[64 * w + 32 + lane] = y;   pay[64 * w + 32 + lane] = yp;
        }
        __syncthreads();

        // ---- cross-warp merge phases k=128,256; j<=32 fused into shfl segments ----
        #pragma unroll 1
        for (int k = 128; k <= MAXC; k <<= 1) {
            #pragma unroll 1
            for (int j = k >> 1; j >= 64; j >>= 1) {
                if (tid < MAXC / 2) {
                    int i = ((tid & ~(j - 1)) << 1) | (tid & (j - 1));
                    int p2 = i | j;
                    u64 a = keys[i], bb = keys[p2];
                    bool desc = ((i & k) == 0);
                    if (desc ? (a < bb) : (a > bb)) {
                        u32 ap = pay[i], bp = pay[p2];
                        keys[i] = bb; keys[p2] = a;
                        pay[i] = bp; pay[p2] = ap;
                    }
                }
                __syncthreads();
            }
            if (w < 4) {
                u64 xx = keys[64 * w + lane];        u32 xxp = pay[64 * w + lane];
                u64 yy = keys[64 * w + 32 + lane];   u32 yyp = pay[64 * w + 32 + lane];
                bool d = (((64 * w) & k) == 0);
                bool xmax = xx > yy;
                if (xmax != d) { u64 tk = xx; xx = yy; yy = tk; u32 tp = xxp; xxp = yyp; yyp = tp; }
                #pragma unroll
                for (int j = 16; j; j >>= 1) { shfl_cmp_kv(xx, xxp, j, d, lane); shfl_cmp_kv(yy, yyp, j, d, lane); }
                keys[64 * w + lane] = xx;        pay[64 * w + lane] = xxp;
                keys[64 * w + 32 + lane] = yy;   pay[64 * w + 32 + lane] = yyp;
            }
            __syncthreads();
        }
    } else {
        // ---- FULL EXACT PATH (statistically never; also covers cnt in (256,512]) ----
        if (tid == 0) s_fcnt = 0;
        for (int i = tid; i < CAP; i += NT) keys[i] = 0ull;
        __syncthreads();
        for (int n = tid; n < NANCH; n += NT) {
            float s = ibase[(size_t)n * NC + 5];
            if (s >= SCORE_TH) {
                int pos = atomicAdd(&s_fcnt, 1);
                if (pos < CAP) keys[pos] = pack_key(s, n);
            }
        }
        __syncthreads();
        M = min(min(s_fcnt, CAP), TOPK);
        for (int k = 2; k <= CAP; k <<= 1)
            for (int j = k >> 1; j; j >>= 1) {
                for (int t = tid; t < CAP / 2; t += NT) {
                    int i = ((t & ~(j - 1)) << 1) | (t & (j - 1));
                    int p = i | j;
                    u64 a = keys[i], bb = keys[p];
                    bool desc = ((i & k) == 0);
                    if (desc ? (a < bb) : (a > bb)) { keys[i] = bb; keys[p] = a; }
                }
                __syncthreads();
            }
    }

    // ---- decode, bit-matrix NMS, scan; with exactness post-check loop ----
    for (int attempt = 0; attempt < 2; ++attempt) {
        u64 ka = (tid < M)      ? keys[tid]      : 0ull;
        u64 kb = (tid + NT < M) ? keys[tid + NT] : 0ull;
        u32 pa = (!full && tid < M) ? pay[tid] : 0u;
        __syncthreads();

        if (!full) {
            if (tid < M) {      // records in smem (prefetched at kernel start)
                float4 r0 = s_rec[2 * pa];
                float4 r1 = s_rec[2 * pa + 1];
                c_box[tid]   = r0;
                cor[tid]     = make_float4(r0.x - r0.z * 0.5f, r0.y - r0.w * 0.5f,
                                           r0.x + r0.z * 0.5f, r0.y + r0.w * 0.5f);
                c_score[tid] = r1.x;
                c_lab[tid]   = r1.y;
            }
        } else {
            #pragma unroll
            for (int half = 0; half < 2; ++half) {
                int i = tid + half * NT;
                u64 kk = half ? kb : ka;
                if (i < M) {
                    int n = (int)(~(u32)kk);
                    float score = __uint_as_float((u32)(kk >> 32) & 0x7fffffffu);
                    int a = n % NA;
                    int cell = n / NA;
                    int gj = cell % GW;
                    int gi = cell / GW;
                    int si = a / 3, ri = a % 3;
                    float s  = 0.5f * (float)(1 << si);
                    float r  = 0.5f * (float)(1 << ri);
                    float sr = sqrtf(r);
                    float ah = (s * sr) * 0.03125f;
                    float aw = (s / sr) * 0.03125f;
                    float ci = ((float)gi + 0.5f) * (1.0f / 128.0f);
                    float cj = ((float)gj + 0.5f) * (1.0f / 128.0f);
                    const float* t = ibase + (size_t)n * NC;
                    float di = ci + t[0] * ah;
                    float dj = cj + t[1] * aw;
                    float dh = ah * expf(t[2]);
                    float dw = aw * expf(t[3]);
                    c_box[i]   = make_float4(di, dj, dh, dw);
                    cor[i]     = make_float4(di - dh * 0.5f, dj - dw * 0.5f,
                                             di + dh * 0.5f, dj + dw * 0.5f);
                    c_score[i] = score;
                    c_idx[i]   = n;
                }
            }
        }
        if (tid == 0) s_any = 0;
        __syncthreads();

        // IoU suppression bit-matrix over first NMSW candidates
        const int Wlim = min(M, NMSW);
        {
            int rrr = tid >> 2, wi = tid & 3;
            u32 mask = 0;
            if (rrr < Wlim) {
                float4 a = cor[rrr];
                float aar = (a.z - a.x) * (a.w - a.y);
                int cbase = wi * 32;
                #pragma unroll 4
                for (int b = 0; b < 32; b++) {
                    int c = cbase + b;
                    if (c > rrr && c < Wlim) {
                        float4 bb = cor[c];
                        float ti = fmaxf(a.x, bb.x), tj = fmaxf(a.y, bb.y);
                        float bi = fminf(a.z, bb.z), bj = fminf(a.w, bb.w);
                        float inter = fmaxf(bi - ti, 0.0f) * fmaxf(bj - tj, 0.0f);
                        float bar = (bb.z - bb.x) * (bb.w - bb.y);
                        float uni = aar + bar - inter;
                        if (inter / fmaxf(uni, 1e-12f) > IOU_TH) mask |= (1u << b);
                    }
                }
            }
            rowsw[rrr][wi] = mask;
            if (tid < 4) rowsw[NMSW][tid] = 0;       // prefetch pad
            if (mask) atomicOr(&s_any, 1u);          // rare
        }
        __syncthreads();

        if (s_any == 0) {
            // zero suppression matrix => greedy keeps the prefix (exact)
            int nk = min(Wlim, MAXDET);
            if (tid < nk) kept_rank[tid] = tid;
            if (tid == 0) s_nk = nk;
        } else if (tid == 0) {
            const uint4* rv = (const uint4*)rowsw;
            u32 s0 = 0, s1 = 0, s2 = 0, s3 = 0;
            int nk = 0;
            uint4 rr = rv[0];
            for (int c = 0; c < Wlim && nk < MAXDET; ++c) {
                uint4 cur = rr;
                rr = rv[c + 1];
                u32 sw = (c < 64) ? ((c < 32) ? s0 : s1) : ((c < 96) ? s2 : s3);
                if (!((sw >> (c & 31)) & 1u)) {
                    kept_rank[nk++] = c;
                    s0 |= cur.x; s1 |= cur.y; s2 |= cur.z; s3 |= cur.w;
                }
            }
            s_nk = nk;
        }
        __syncthreads();

        // rare: continue serial greedy NMS past the window
        if (s_nk < MAXDET && M > Wlim) {
            if (tid < 32) {
                int nk = s_nk;
                float kc0[4], kc1[4], kc2[4], kc3[4], kar[4];
                #pragma unroll
                for (int sdx = 0; sdx < 4; ++sdx) {
                    int k = sdx * 32 + lane;
                    if (k < nk) {
                        float4 a = cor[kept_rank[k]];
                        kc0[sdx] = a.x; kc1[sdx] = a.y; kc2[sdx] = a.z; kc3[sdx] = a.w;
                        kar[sdx] = (a.z - a.x) * (a.w - a.y);
                    }
                }
                #pragma unroll 1
                for (int c = Wlim; c < M && nk < MAXDET; ++c) {
                    float4 a = cor[c];
                    float ar = (a.z - a.x) * (a.w - a.y);
                    bool pred = false;
                    #pragma unroll
                    for (int sdx = 0; sdx < 4; ++sdx) {
                        int k = sdx * 32 + lane;
                        if (k < nk) {
                            float ti = fmaxf(a.x, kc0[sdx]);
                            float tj = fmaxf(a.y, kc1[sdx]);
                            float bi = fminf(a.z, kc2[sdx]);
                            float bj = fminf(a.w, kc3[sdx]);
                            float inter = fmaxf(bi - ti, 0.0f) * fmaxf(bj - tj, 0.0f);
                            float uni = kar[sdx] + ar - inter;
                            pred |= (inter / fmaxf(uni, 1e-12f)) > IOU_TH;
                        }
                    }
                    if (!__ballot_sync(0xffffffffu, pred)) {
                        int slot = nk >> 5, ln = nk & 31;
                        if (lane == ln) {
                            #pragma unroll
                            for (int sdx = 0; sdx < 4; ++sdx) {
                                if (slot == sdx) {
                                    kc0[sdx] = a.x; kc1[sdx] = a.y;
                                    kc2[sdx] = a.z; kc3[sdx] = a.w; kar[sdx] = ar;
                                }
                            }
                            kept_rank[nk] = c;
                        }
                        nk++;
                    }
                }
                if (lane == 0) s_nk = nk;
            }
            __syncthreads();
        }

        // exactness post-check: fast set exhausted with <100 kept -> redo on full set
        if (tid == 0) s_flag = (!full && attempt == 0 && s_nk < MAXDET) ? 1 : 0;
        __syncthreads();
        if (!s_flag) break;

        full = true;
        if (tid == 0) s_fcnt = 0;
        __syncthreads();
        for (int i = tid; i < CAP; i += NT) keys[i] = 0ull;
        __syncthreads();
        for (int n = tid; n < NANCH; n += NT) {
            float s = ibase[(size_t)n * NC + 5];
            if (s >= SCORE_TH) {
                int pos = atomicAdd(&s_fcnt, 1);
                if (pos < CAP) keys[pos] = pack_key(s, n);
            }
        }
        __syncthreads();
        M = min(min(s_fcnt, CAP), TOPK);
        for (int k = 2; k <= CAP; k <<= 1)
            for (int j = k >> 1; j; j >>= 1) {
                for (int t = tid; t < CAP / 2; t += NT) {
                    int i = ((t & ~(j - 1)) << 1) | (t & (j - 1));
                    int p = i | j;
                    u64 a = keys[i], bb = keys[p];
                    bool desc = ((i & k) == 0);
                    if (desc ? (a < bb) : (a > bb)) { keys[i] = bb; keys[p] = a; }
                }
                __syncthreads();
            }
    }

    // ---- epilogue ----
    const int nk = s_nk;
    if (!full) {
        if (tid < MAXDET) {
            float* o = out + (size_t)img * MAXDET * 6 + tid * 6;
            if (tid < nk) {
                int c = kept_rank[tid];
                float4 bx = c_box[c];
                o[0] = bx.x; o[1] = bx.y; o[2] = bx.z; o[3] = bx.w;
                o[4] = c_lab[c];
                o[5] = c_score[c];
            } else {
                o[0] = 0.0f; o[1] = 0.0f; o[2] = 0.0f;
                o[3] = 0.0f; o[4] = 0.0f; o[5] = 0.0f;
            }
        }
    } else {
        #pragma unroll 1
        for (int row = tid >> 3; row < MAXDET; row += NT / 8) {
            const int sub = tid & 7;
            float* o = out + (size_t)img * MAXDET * 6 + row * 6;
            const bool live = row < nk;
            int c = live ? kept_rank[row] : 0;
            int n = live ? c_idx[c] : 0;
            float bv = -1e38f; int bidx = 1 << 30;
            if (live) {
                const float* cls = ibase + (size_t)n * NC + 6;
                #pragma unroll
                for (int t = 0; t < 10; t++) {
                    int cc = sub + t * 8;
                    float v = __ldg(cls + cc);
                    if (v > bv) { bv = v; bidx = cc; }
                }
            }
            #pragma unroll
            for (int off = 4; off; off >>= 1) {
                float ov = __shfl_down_sync(0xffffffffu, bv, off, 8);
                int   oi = __shfl_down_sync(0xffffffffu, bidx, off, 8);
                if (ov > bv || (ov == bv && oi < bidx)) { bv = ov; bidx = oi; }
            }
            if (live) {
                if (sub == 0) {
                    float4 bx = c_box[c];
                    o[0] = bx.x; o[1] = bx.y; o[2] = bx.z; o[3] = bx.w;
                    o[4] = (float)bidx;
                    o[5] = c_score[c];
                }
            } else {
                if (sub < 6) o[sub] = 0.0f;
            }
        }
    }
}

extern "C" void kernel_launch(void* const* d_in, const int* in_sizes, int n_in,
                              void* d_out, int out_size) {
    (void)in_sizes; (void)n_in; (void)out_size;
    const float* in = (const float*)d_in[0];
    float* out = (float*)d_out;

    prefilter_kernel<<<dim3(K1B, NIMG), K1T>>>(in);
    topk_nms_kernel<<<NIMG, NT>>>(in, out);
}

// round 16
// speedup vs baseline: 1.1739x; 1.1739x over previous
#include <cuda_runtime.h>
#include <cstdint>
#include <math.h>

#define NIMG     8
#define GH       128
#define GW       128
#define NA       9
#define NANCH    (GH*GW*NA)      /* 147456 */
#define NC       86
#define CAPF     512             /* candidate capacity */
#define CAP      2048            /* full-fallback cap */
#define PRE_T    3.0f            /* expected count ~199 +/- 14; [128,256] at -5/+4 sigma */
#define MINC     128
#define MAXC     256             /* fast path upper bound (sort width) */
#define TOPK     1000
#define MAXDET   100
#define SCORE_TH 0.5f
#define IOU_TH   0.75f
#define NMSW     128             /* IoU bit-matrix window */
#define NT       512             /* block size */
#define K1T      512             /* prefilter threads */
#define K1PER    16              /* anchors per prefilter thread (front-batched MLP=16) */
#define K1B      (NANCH / (K1T * K1PER))   /* 18 blocks/image -> 144 CTAs = ONE wave */

typedef unsigned long long u64;
typedef unsigned int       u32;

__device__ u64 g_buf[NIMG][CAPF];
__device__ __align__(16) float g_rec[NIMG][CAPF][8];  /* di,dj,dh,dw,score,label,-,- */
__device__ int g_cnt[NIMG];

static __device__ __forceinline__ u64 pack_key(float s, int n) {
    // s >= 0.5 > 0 -> orderable bits = bits|sign. DESCENDING sort; low word = ~n
    // gives "smaller index first" on ties (lax.top_k semantics).
    u32 sb = __float_as_uint(s) | 0x80000000u;
    return ((u64)sb << 32) | (u32)(~n);
}

// ===================== K1: single-wave prefilter (DRAM-floor scan) + per-hit records =====================
__global__ __launch_bounds__(K1T, 1)
void prefilter_kernel(const float* __restrict__ in) {
    __shared__ uint4 hitlist[CAPF];   // appends gated by slot<CAPF => no overflow
    __shared__ int s_hc;

    const int img = blockIdx.y;
    const int tid = threadIdx.x;
    const float* ibase = in + (size_t)img * NANCH * NC;

    if (tid == 0) s_hc = 0;
    __syncthreads();

    // front-batched MLP=16 scan of this CTA's 8192-anchor slice
    const int base = blockIdx.x * (K1T * K1PER);
    float v[K1PER];
    #pragma unroll
    for (int k = 0; k < K1PER; k++)
        v[k] = __ldg(ibase + (size_t)(base + tid + k * K1T) * NC + 5);
    #pragma unroll
    for (int k = 0; k < K1PER; k++) {
        if (v[k] >= PRE_T) {
            int n = base + tid + k * K1T;
            int p = atomicAdd(&g_cnt[img], 1);
            if (p < CAPF) {
                g_buf[img][p] = pack_key(v[k], n);
                int h = atomicAdd(&s_hc, 1);
                hitlist[h] = make_uint4((u32)p, (u32)n, __float_as_uint(v[k]), 0u);
            }
        }
    }
    __syncthreads();

    // post-pass: one WARP per hit -> parallel class argmax + box decode -> g_rec
    const int hc = s_hc;                 // ~14 per CTA typically
    const int w = tid >> 5, lane = tid & 31;
    for (int h = w; h < hc; h += K1T / 32) {
        uint4 e = hitlist[h];
        const int n = (int)e.y;
        const float* row = ibase + (size_t)n * NC;
        float bv = __ldg(row + 6 + lane);
        int bidx = lane;
        float v1 = __ldg(row + 6 + 32 + lane);
        float v2 = (lane < 16) ? __ldg(row + 6 + 64 + lane) : -1e38f;
        if (v1 > bv) { bv = v1; bidx = 32 + lane; }
        if (v2 > bv) { bv = v2; bidx = 64 + lane; }
        #pragma unroll
        for (int off = 16; off; off >>= 1) {
            float ov = __shfl_down_sync(0xffffffffu, bv, off);
            int   oi = __shfl_down_sync(0xffffffffu, bidx, off);
            if (ov > bv || (ov == bv && oi < bidx)) { bv = ov; bidx = oi; }
        }
        if (lane == 0) {
            int a = n % NA;
            int cell = n / NA;
            int gj = cell % GW;
            int gi = cell / GW;
            int si = a / 3, ri = a % 3;
            float s  = 0.5f * (float)(1 << si);
            float r  = 0.5f * (float)(1 << ri);
            float sr = sqrtf(r);
            float ah = (s * sr) * 0.03125f;          // ANCHOR_BASE_CELLS / 128
            float aw = (s / sr) * 0.03125f;
            float ci = ((float)gi + 0.5f) * (1.0f / 128.0f);
            float cj = ((float)gj + 0.5f) * (1.0f / 128.0f);
            float2 t01 = *(const float2*)row;
            float2 t23 = *(const float2*)(row + 2);
            float di = ci + t01.x * ah;
            float dj = cj + t01.y * aw;
            float dh = ah * expf(t23.x);
            float dw = aw * expf(t23.y);
            float* rec = &g_rec[img][e.x][0];
            *(float4*)rec       = make_float4(di, dj, dh, dw);
            *(float2*)(rec + 4) = make_float2(__uint_as_float(e.z), (float)bidx);
        }
    }
}

// ===================== K2: straight-line fast path, instruction-trimmed =====================
static __device__ __forceinline__ void shfl_cmp_kv(u64& k, u32& p, int j, bool desc, int lane) {
    u64 ok = __shfl_xor_sync(0xffffffffu, k, j);
    u32 op = __shfl_xor_sync(0xffffffffu, p, j);
    bool upper = (lane & j) == 0;                   // smaller-index position
    bool keep_max = (upper == desc);
    bool mine_max = k > ok;
    if (keep_max != mine_max) { k = ok; p = op; }
}

__global__ __launch_bounds__(NT, 1)
void topk_nms_kernel(const float* __restrict__ in, float* __restrict__ out) {
    __shared__ __align__(16) u64 keys[CAP];          // sorted keys; overlaid by cor[] after decode
    __shared__ u32  pay[CAPF];
    __shared__ __align__(16) float4 s_rec[MAXC * 2]; // smem copy of g_rec slots 0..255 (fast path)
    __shared__ __align__(16) float4 c_box[1024];
    __shared__ float c_score[1024];
    __shared__ float c_lab[1024];
    __shared__ int   c_idx[1024];                    // full-fallback only
    __shared__ __align__(16) u32 rowsw[NMSW + 1][4];
    __shared__ int   kept_rank[MAXDET];
    __shared__ int   s_nk;
    __shared__ int   s_fcnt;
    __shared__ u32   s_any;

    const int img = blockIdx.x;
    const int tid = threadIdx.x;
    const int w = tid >> 5, lane = tid & 31;
    const float* ibase = in + (size_t)img * NANCH * NC;
    float4* cor = (float4*)keys;

    // ---- front-batched head ----
    u64 x = 0, y = 0; u32 xp = 0, yp = 0;
    if (w < 4) {
        int i0 = 64 * w + lane;
        xp = i0; yp = i0 + 32;
        x = g_buf[img][i0];
        y = g_buf[img][i0 + 32];
    } else {
        int t0 = tid - 128;
        const float4* src = (const float4*)&g_rec[img][0][0];
        #pragma unroll
        for (int r = 0; r < 2; r++) {
            int i = t0 + r * 384;
            if (i < MAXC * 2) s_rec[i] = src[i];
        }
    }
    int cnt = g_cnt[img];
    __syncthreads();
    if (tid == 0) g_cnt[img] = 0;        // reset for next replay (stream-ordered)

    bool full = !(cnt >= MINC && cnt <= MAXC);
    int M = 0;

    // =================== FAST PATH (straight-line) ===================
    if (!full) {
        M = cnt;
        if (w < 4) {
            int i0 = 64 * w + lane;
            if (i0 >= cnt)      x = 0ull;
            if (i0 + 32 >= cnt) y = 0ull;

            // per-warp 64-element register bitonic sort (block w desc iff w even)
            const bool block_desc = ((w & 1) == 0);
            const bool flip = !block_desc;
            #pragma unroll
            for (int k = 2; k <= 16; k <<= 1)
                #pragma unroll
                for (int j = k >> 1; j; j >>= 1) {
                    bool d = (((lane & k) == 0) != flip);
                    shfl_cmp_kv(x, xp, j, d, lane);
                    shfl_cmp_kv(y, yp, j, d, lane);
                }
            { // k=32: halves opposite directions
                bool dx = !flip, dy = flip;
                #pragma unroll
                for (int j = 16; j; j >>= 1) { shfl_cmp_kv(x, xp, j, dx, lane); shfl_cmp_kv(y, yp, j, dy, lane); }
            }
            { // k=64
                bool d = block_desc;
                bool xmax = x > y;
                if (xmax != d) { u64 tk = x; x = y; y = tk; u32 tp = xp; xp = yp; yp = tp; }
                #pragma unroll
                for (int j = 16; j; j >>= 1) { shfl_cmp_kv(x, xp, j, d, lane); shfl_cmp_kv(y, yp, j, d, lane); }
            }
            keys[64 * w + lane] = x;        pay[64 * w + lane] = xp;
            keys[64 * w + 32 + lane] = y;   pay[64 * w + 32 + lane] = yp;
        }
        __syncthreads();

        // cross-warp merge phases k=128,256; j<=32 fused into shfl segments
        #pragma unroll 1
        for (int k = 128; k <= MAXC; k <<= 1) {
            #pragma unroll 1
            for (int j = k >> 1; j >= 64; j >>= 1) {
                if (tid < MAXC / 2) {
                    int i = ((tid & ~(j - 1)) << 1) | (tid & (j - 1));
                    int p2 = i | j;
                    u64 a = keys[i], bb = keys[p2];
                    bool desc = ((i & k) == 0);
                    if (desc ? (a < bb) : (a > bb)) {
                        u32 ap = pay[i], bp = pay[p2];
                        keys[i] = bb; keys[p2] = a;
                        pay[i] = bp; pay[p2] = ap;
                    }
                }
                __syncthreads();
            }
            if (w < 4) {
                u64 xx = keys[64 * w + lane];        u32 xxp = pay[64 * w + lane];
                u64 yy = keys[64 * w + 32 + lane];   u32 yyp = pay[64 * w + 32 + lane];
                bool d = (((64 * w) & k) == 0);
                bool xmax = xx > yy;
                if (xmax != d) { u64 tk = xx; xx = yy; yy = tk; u32 tp = xxp; xxp = yyp; yyp = tp; }
                #pragma unroll
                for (int j = 16; j; j >>= 1) { shfl_cmp_kv(xx, xxp, j, d, lane); shfl_cmp_kv(yy, yyp, j, d, lane); }
                keys[64 * w + lane] = xx;        pay[64 * w + lane] = xxp;
                keys[64 * w + 32 + lane] = yy;   pay[64 * w + 32 + lane] = yyp;
            }
            __syncthreads();
        }

        // ---- decode from smem records (keys dead; cor overlay safe, no extra barrier) ----
        if (tid < M) {
            u32 pa = pay[tid];
            float4 r0 = s_rec[2 * pa];
            float4 r1 = s_rec[2 * pa + 1];
            c_box[tid]   = r0;
            cor[tid]     = make_float4(r0.x - r0.z * 0.5f, r0.y - r0.w * 0.5f,
                                       r0.x + r0.z * 0.5f, r0.y + r0.w * 0.5f);
            c_score[tid] = r1.x;
            c_lab[tid]   = r1.y;
        }
        if (tid == 0) s_any = 0;
        __syncthreads();

        // ---- fast IoU bit-matrix: Wlim==128 guaranteed; branchless + closing range mask ----
        {
            int rrr = tid >> 2, wi = tid & 3;
            int cbase = wi * 32;
            int lo = rrr - cbase;            // bits b<=lo are c<=rrr (to clear)
            u32 mask = 0;
            if (lo < 31) {                   // word has at least one valid bit
                float4 a = cor[rrr];
                float aar = (a.z - a.x) * (a.w - a.y);
                #pragma unroll 8
                for (int b = 0; b < 32; b++) {
                    float4 bb = cor[cbase + b];
                    float ti = fmaxf(a.x, bb.x), tj = fmaxf(a.y, bb.y);
                    float bi = fminf(a.z, bb.z), bj = fminf(a.w, bb.w);
                    float inter = fmaxf(bi - ti, 0.0f) * fmaxf(bj - tj, 0.0f);
                    float bar = (bb.z - bb.x) * (bb.w - bb.y);
                    float den = fmaxf(aar + bar - inter, 1e-12f);
                    if (inter > IOU_TH * den) mask |= (1u << b);
                }
                if (lo >= 0) mask &= ~((2u << lo) - 1u);
            }
            rowsw[rrr][wi] = mask;
            if (tid < 4) rowsw[NMSW][tid] = 0;
            if (mask) atomicOr(&s_any, 1u);  // rare
        }
        __syncthreads();

        if (s_any == 0) {
            // zero matrix => greedy keeps the prefix (exact); M>=128 => nk=100
            if (tid < MAXDET) kept_rank[tid] = tid;
            if (tid == 0) s_nk = MAXDET;
        } else if (tid == 0) {
            const uint4* rv = (const uint4*)rowsw;
            u32 s0 = 0, s1 = 0, s2 = 0, s3 = 0;
            int nk = 0;
            uint4 rr = rv[0];
            for (int c = 0; c < NMSW && nk < MAXDET; ++c) {
                uint4 cur = rr;
                rr = rv[c + 1];
                u32 sw = (c < 64) ? ((c < 32) ? s0 : s1) : ((c < 96) ? s2 : s3);
                if (!((sw >> (c & 31)) & 1u)) {
                    kept_rank[nk++] = c;
                    s0 |= cur.x; s1 |= cur.y; s2 |= cur.z; s3 |= cur.w;
                }
            }
            s_nk = nk;
        }
        __syncthreads();

        // exactness post-check: window exhausted with <100 kept -> redo on the FULL set
        if (s_nk < MAXDET) full = true;
    }

    // =================== FULL EXACT PATH (statistically never) ===================
    if (full) {
        if (tid == 0) s_fcnt = 0;
        for (int i = tid; i < CAP; i += NT) keys[i] = 0ull;
        __syncthreads();
        for (int n = tid; n < NANCH; n += NT) {
            float s = ibase[(size_t)n * NC + 5];
            if (s >= SCORE_TH) {
                int pos = atomicAdd(&s_fcnt, 1);
                if (pos < CAP) keys[pos] = pack_key(s, n);
            }
        }
        __syncthreads();
        M = min(min(s_fcnt, CAP), TOPK);
        for (int k = 2; k <= CAP; k <<= 1)
            for (int j = k >> 1; j; j >>= 1) {
                for (int t = tid; t < CAP / 2; t += NT) {
                    int i = ((t & ~(j - 1)) << 1) | (t & (j - 1));
                    int p = i | j;
                    u64 a = keys[i], bb = keys[p];
                    bool desc = ((i & k) == 0);
                    if (desc ? (a < bb) : (a > bb)) { keys[i] = bb; keys[p] = a; }
                }
                __syncthreads();
            }

        // full decode (keys read to regs, then cor overlays)
        u64 ka = (tid < M)      ? keys[tid]      : 0ull;
        u64 kb = (tid + NT < M) ? keys[tid + NT] : 0ull;
        __syncthreads();
        #pragma unroll
        for (int half = 0; half < 2; ++half) {
            int i = tid + half * NT;
            u64 kk = half ? kb : ka;
            if (i < M) {
                int n = (int)(~(u32)kk);
                float score = __uint_as_float((u32)(kk >> 32) & 0x7fffffffu);
                int a = n % NA;
                int cell = n / NA;
                int gj = cell % GW;
                int gi = cell / GW;
                int si = a / 3, ri = a % 3;
                float s  = 0.5f * (float)(1 << si);
                float r  = 0.5f * (float)(1 << ri);
                float sr = sqrtf(r);
                float ah = (s * sr) * 0.03125f;
                float aw = (s / sr) * 0.03125f;
                float ci = ((float)gi + 0.5f) * (1.0f / 128.0f);
                float cj = ((float)gj + 0.5f) * (1.0f / 128.0f);
                const float* t = ibase + (size_t)n * NC;
                float di = ci + t[0] * ah;
                float dj = cj + t[1] * aw;
                float dh = ah * expf(t[2]);
                float dw = aw * expf(t[3]);
                c_box[i]   = make_float4(di, dj, dh, dw);
                cor[i]     = make_float4(di - dh * 0.5f, dj - dw * 0.5f,
                                         di + dh * 0.5f, dj + dw * 0.5f);
                c_score[i] = score;
                c_idx[i]   = n;
            }
        }
        if (tid == 0) s_any = 0;
        __syncthreads();

        // general bit-matrix (predicated; Wlim may be < 128)
        const int Wlim = min(M, NMSW);
        {
            int rrr = tid >> 2, wi = tid & 3;
            u32 mask = 0;
            if (rrr < Wlim) {
                float4 a = cor[rrr];
                float aar = (a.z - a.x) * (a.w - a.y);
                int cbase = wi * 32;
                #pragma unroll 4
                for (int b = 0; b < 32; b++) {
                    int c = cbase + b;
                    if (c > rrr && c < Wlim) {
                        float4 bb = cor[c];
                        float ti = fmaxf(a.x, bb.x), tj = fmaxf(a.y, bb.y);
                        float bi = fminf(a.z, bb.z), bj = fminf(a.w, bb.w);
                        float inter = fmaxf(bi - ti, 0.0f) * fmaxf(bj - tj, 0.0f);
                        float bar = (bb.z - bb.x) * (bb.w - bb.y);
                        float den = fmaxf(aar + bar - inter, 1e-12f);
                        if (inter > IOU_TH * den) mask |= (1u << b);
                    }
                }
            }
            rowsw[rrr][wi] = mask;
            if (tid < 4) rowsw[NMSW][tid] = 0;
            if (mask) atomicOr(&s_any, 1u);
        }
        __syncthreads();

        if (s_any == 0) {
            int nk = min(Wlim, MAXDET);
            if (tid < nk) kept_rank[tid] = tid;
            if (tid == 0) s_nk = nk;
        } else if (tid == 0) {
            const uint4* rv = (const uint4*)rowsw;
            u32 s0 = 0, s1 = 0, s2 = 0, s3 = 0;
            int nk = 0;
            uint4 rr = rv[0];
            for (int c = 0; c < Wlim && nk < MAXDET; ++c) {
                uint4 cur = rr;
                rr = rv[c + 1];
                u32 sw = (c < 64) ? ((c < 32) ? s0 : s1) : ((c < 96) ? s2 : s3);
                if (!((sw >> (c & 31)) & 1u)) {
                    kept_rank[nk++] = c;
                    s0 |= cur.x; s1 |= cur.y; s2 |= cur.z; s3 |= cur.w;
                }
            }
            s_nk = nk;
        }
        __syncthreads();

        // serial greedy NMS past the window (kept list in registers)
        if (s_nk < MAXDET && M > Wlim) {
            if (tid < 32) {
                int nk = s_nk;
                float kc0[4], kc1[4], kc2[4], kc3[4], kar[4];
                #pragma unroll
                for (int sdx = 0; sdx < 4; ++sdx) {
                    int k = sdx * 32 + lane;
                    if (k < nk) {
                        float4 a = cor[kept_rank[k]];
                        kc0[sdx] = a.x; kc1[sdx] = a.y; kc2[sdx] = a.z; kc3[sdx] = a.w;
                        kar[sdx] = (a.z - a.x) * (a.w - a.y);
                    }
                }
                #pragma unroll 1
                for (int c = Wlim; c < M && nk < MAXDET; ++c) {
                    float4 a = cor[c];
                    float ar = (a.z - a.x) * (a.w - a.y);
                    bool pred = false;
                    #pragma unroll
                    for (int sdx = 0; sdx < 4; ++sdx) {
                        int k = sdx * 32 + lane;
                        if (k < nk) {
                            float ti = fmaxf(a.x, kc0[sdx]);
                            float tj = fmaxf(a.y, kc1[sdx]);
                            float bi = fminf(a.z, kc2[sdx]);
                            float bj = fminf(a.w, kc3[sdx]);
                            float inter = fmaxf(bi - ti, 0.0f) * fmaxf(bj - tj, 0.0f);
                            float den = fmaxf(kar[sdx] + ar - inter, 1e-12f);
                            pred |= inter > IOU_TH * den;
                        }
                    }
                    if (!__ballot_sync(0xffffffffu, pred)) {
                        int slot = nk >> 5, ln = nk & 31;
                        if (lane == ln) {
                            #pragma unroll
                            for (int sdx = 0; sdx < 4; ++sdx) {
                                if (slot == sdx) {
                                    kc0[sdx] = a.x; kc1[sdx] = a.y;
                                    kc2[sdx] = a.z; kc3[sdx] = a.w; kar[sdx] = ar;
                                }
                            }
                            kept_rank[nk] = c;
                        }
                        nk++;
                    }
                }
                if (lane == 0) s_nk = nk;
            }
            __syncthreads();
        }
    }

    // ---- epilogue ----
    const int nk = s_nk;
    if (!full) {
        if (tid < MAXDET) {
            float* o = out + (size_t)img * MAXDET * 6 + tid * 6;
            if (tid < nk) {
                int c = kept_rank[tid];
                float4 bx = c_box[c];
                o[0] = bx.x; o[1] = bx.y; o[2] = bx.z; o[3] = bx.w;
                o[4] = c_lab[c];
                o[5] = c_score[c];
            } else {
                o[0] = 0.0f; o[1] = 0.0f; o[2] = 0.0f;
                o[3] = 0.0f; o[4] = 0.0f; o[5] = 0.0f;
            }
        }
    } else {
        #pragma unroll 1
        for (int row = tid >> 3; row < MAXDET; row += NT / 8) {
            const int sub = tid & 7;
            float* o = out + (size_t)img * MAXDET * 6 + row * 6;
            const bool live = row < nk;
            int c = live ? kept_rank[row] : 0;
            int n = live ? c_idx[c] : 0;
            float bv = -1e38f; int bidx = 1 << 30;
            if (live) {
                const float* cls = ibase + (size_t)n * NC + 6;
                #pragma unroll
                for (int t = 0; t < 10; t++) {
                    int cc = sub + t * 8;
                    float v = __ldg(cls + cc);
                    if (v > bv) { bv = v; bidx = cc; }
                }
            }
            #pragma unroll
            for (int off = 4; off; off >>= 1) {
                float ov = __shfl_down_sync(0xffffffffu, bv, off, 8);
                int   oi = __shfl_down_sync(0xffffffffu, bidx, off, 8);
                if (ov > bv || (ov == bv && oi < bidx)) { bv = ov; bidx = oi; }
            }
            if (live) {
                if (sub == 0) {
                    float4 bx = c_box[c];
                    o[0] = bx.x; o[1] = bx.y; o[2] = bx.z; o[3] = bx.w;
                    o[4] = (float)bidx;
                    o[5] = c_score[c];
                }
            } else {
                if (sub < 6) o[sub] = 0.0f;
            }
        }
    }
}

extern "C" void kernel_launch(void* const* d_in, const int* in_sizes, int n_in,
                              void* d_out, int out_size) {
    (void)in_sizes; (void)n_in; (void)out_size;
    const float* in = (const float*)d_in[0];
    float* out = (float*)d_out;

    prefilter_kernel<<<dim3(K1B, NIMG), K1T>>>(in);
    topk_nms_kernel<<<NIMG, NT>>>(in, out);
}

// round 17
// speedup vs baseline: 1.1750x; 1.0009x over previous
#include <cuda_runtime.h>
#include <cstdint>
#include <math.h>

#define NIMG     8
#define GH       128
#define GW       128
#define NA       9
#define NANCH    (GH*GW*NA)      /* 147456 */
#define NC       86
#define CAPF     512             /* candidate capacity */
#define CAP      2048            /* full-fallback cap */
#define PRE_T    3.0f            /* expected count ~199 +/- 14; [128,256] at -5/+4 sigma */
#define MINC     128
#define MAXC     256             /* fast path upper bound (sort width) */
#define TOPK     1000
#define MAXDET   100
#define SCORE_TH 0.5f
#define IOU_TH   0.75f
#define NMSW     128             /* IoU bit-matrix window */
#define NT       512             /* block size */
#define PCTA     18              /* 8*18=144 CTAs <= 148 SMs: co-resident, spin-safe */
#define SLICE    (NANCH / PCTA)  /* 8192 anchors per CTA */
#define PERTHR   (SLICE / NT)    /* 16 anchors per thread */

typedef unsigned long long u64;
typedef unsigned int       u32;

__device__ u64 g_buf[NIMG][CAPF];
__device__ __align__(16) float g_rec[NIMG][CAPF][8];  /* di,dj,dh,dw,score,label,-,- */
__device__ int g_cnt[NIMG];
__device__ int g_done[NIMG];

static __device__ __forceinline__ u64 pack_key(float s, int n) {
    // s >= 0.5 > 0 -> orderable bits = bits|sign. DESCENDING sort; low word = ~n
    // gives "smaller index first" on ties (lax.top_k semantics).
    u32 sb = __float_as_uint(s) | 0x80000000u;
    return ((u64)sb << 32) | (u32)(~n);
}

static __device__ __forceinline__ void shfl_cmp_kv(u64& k, u32& p, int j, bool desc, int lane) {
    u64 ok = __shfl_xor_sync(0xffffffffu, k, j);
    u32 op = __shfl_xor_sync(0xffffffffu, p, j);
    bool upper = (lane & j) == 0;                   // smaller-index position
    bool keep_max = (upper == desc);
    bool mine_max = k > ok;
    if (keep_max != mine_max) { k = ok; p = op; }
}

__global__ __launch_bounds__(NT, 1)
void fused_kernel(const float* __restrict__ in, float* __restrict__ out) {
    __shared__ __align__(16) u64 keys[CAP];          // sorted keys; overlaid by cor[] after decode
    __shared__ u32  pay[CAPF];
    __shared__ __align__(16) float4 s_rec[MAXC * 2]; // smem copy of g_rec slots 0..255 (fast path)
    __shared__ __align__(16) float4 c_box[1024];     // ALSO aliases phase-A hitlist
    __shared__ float c_score[1024];
    __shared__ float c_lab[1024];
    __shared__ int   c_idx[1024];                    // full-fallback only
    __shared__ __align__(16) u32 rowsw[NMSW + 1][4];
    __shared__ int   kept_rank[MAXDET];
    __shared__ int   s_nk;
    __shared__ int   s_fcnt;
    __shared__ u32   s_any;
    __shared__ int   s_hc;

    const int img   = blockIdx.x / PCTA;
    const int slice = blockIdx.x % PCTA;
    const int tid = threadIdx.x;
    const int w = tid >> 5, lane = tid & 31;
    const float* ibase = in + (size_t)img * NANCH * NC;
    float4* cor = (float4*)keys;
    uint4* hitlist = (uint4*)c_box;                  // phase-disjoint alias (phase A only)

    // ================= PHASE A: prefilter slice (DRAM floor) + hit records =================
    {
        if (tid == 0) s_hc = 0;
        __syncthreads();

        const int base = slice * SLICE;
        float v[PERTHR];
        #pragma unroll
        for (int k = 0; k < PERTHR; k++)
            v[k] = __ldg(ibase + (size_t)(base + tid + k * NT) * NC + 5);
        #pragma unroll
        for (int k = 0; k < PERTHR; k++) {
            if (v[k] >= PRE_T) {
                int n = base + tid + k * NT;
                int p = atomicAdd(&g_cnt[img], 1);
                if (p < CAPF) {
                    g_buf[img][p] = pack_key(v[k], n);
                    int h = atomicAdd(&s_hc, 1);
                    hitlist[h] = make_uint4((u32)p, (u32)n, __float_as_uint(v[k]), 0u);
                }
            }
        }
        __syncthreads();

        // post-pass: one WARP per hit -> parallel class argmax + box decode -> g_rec
        const int hc = s_hc;             // ~11 per CTA typically
        for (int h = w; h < hc; h += NT / 32) {
            uint4 e = hitlist[h];
            const int n = (int)e.y;
            const float* row = ibase + (size_t)n * NC;
            float bv = __ldg(row + 6 + lane);
            int bidx = lane;
            float v1 = __ldg(row + 6 + 32 + lane);
            float v2 = (lane < 16) ? __ldg(row + 6 + 64 + lane) : -1e38f;
            if (v1 > bv) { bv = v1; bidx = 32 + lane; }
            if (v2 > bv) { bv = v2; bidx = 64 + lane; }
            #pragma unroll
            for (int off = 16; off; off >>= 1) {
                float ov = __shfl_down_sync(0xffffffffu, bv, off);
                int   oi = __shfl_down_sync(0xffffffffu, bidx, off);
                if (ov > bv || (ov == bv && oi < bidx)) { bv = ov; bidx = oi; }
            }
            if (lane == 0) {
                int a = n % NA;
                int cell = n / NA;
                int gj = cell % GW;
                int gi = cell / GW;
                int si = a / 3, ri = a % 3;
                float s  = 0.5f * (float)(1 << si);
                float r  = 0.5f * (float)(1 << ri);
                float sr = sqrtf(r);
                float ah = (s * sr) * 0.03125f;      // ANCHOR_BASE_CELLS / 128
                float aw = (s / sr) * 0.03125f;
                float ci = ((float)gi + 0.5f) * (1.0f / 128.0f);
                float cj = ((float)gj + 0.5f) * (1.0f / 128.0f);
                float2 t01 = *(const float2*)row;
                float2 t23 = *(const float2*)(row + 2);
                float di = ci + t01.x * ah;
                float dj = cj + t01.y * aw;
                float dh = ah * expf(t23.x);
                float dw = aw * expf(t23.y);
                float* rec = &g_rec[img][e.x][0];
                *(float4*)rec       = make_float4(di, dj, dh, dw);
                *(float2*)(rec + 4) = make_float2(__uint_as_float(e.z), (float)bidx);
            }
        }
        __syncthreads();
        if (tid == 0) { __threadfence(); atomicAdd(&g_done[img], 1); }
        if (slice != 0) return;          // producers done; 8 consumer CTAs continue
    }

    // ================= consumer: wait for this image's producers =================
    if (tid == 0) {
        while (atomicAdd(&g_done[img], 0) < PCTA) { }
    }
    __syncthreads();
    __threadfence();                     // acquire: g_buf/g_rec/g_cnt visible

    // ---- front-batched head (L2-hot) ----
    u64 x = 0, y = 0; u32 xp = 0, yp = 0;
    if (w < 4) {
        int i0 = 64 * w + lane;
        xp = i0; yp = i0 + 32;
        x = g_buf[img][i0];
        y = g_buf[img][i0 + 32];
    } else {
        int t0 = tid - 128;
        const float4* src = (const float4*)&g_rec[img][0][0];
        #pragma unroll
        for (int r = 0; r < 2; r++) {
            int i = t0 + r * 384;
            if (i < MAXC * 2) s_rec[i] = src[i];
        }
    }
    int cnt = *((volatile int*)&g_cnt[img]);
    __syncthreads();
    if (tid == 0) { g_cnt[img] = 0; g_done[img] = 0; }   // reset for next replay

    bool full = !(cnt >= MINC && cnt <= MAXC);
    int M = 0;

    // =================== FAST PATH (straight-line) ===================
    if (!full) {
        M = cnt;
        if (w < 4) {
            int i0 = 64 * w + lane;
            if (i0 >= cnt)      x = 0ull;
            if (i0 + 32 >= cnt) y = 0ull;

            // per-warp 64-element register bitonic sort (block w desc iff w even)
            const bool block_desc = ((w & 1) == 0);
            const bool flip = !block_desc;
            #pragma unroll
            for (int k = 2; k <= 16; k <<= 1)
                #pragma unroll
                for (int j = k >> 1; j; j >>= 1) {
                    bool d = (((lane & k) == 0) != flip);
                    shfl_cmp_kv(x, xp, j, d, lane);
                    shfl_cmp_kv(y, yp, j, d, lane);
                }
            { // k=32: halves opposite directions
                bool dx = !flip, dy = flip;
                #pragma unroll
                for (int j = 16; j; j >>= 1) { shfl_cmp_kv(x, xp, j, dx, lane); shfl_cmp_kv(y, yp, j, dy, lane); }
            }
            { // k=64
                bool d = block_desc;
                bool xmax = x > y;
                if (xmax != d) { u64 tk = x; x = y; y = tk; u32 tp = xp; xp = yp; yp = tp; }
                #pragma unroll
                for (int j = 16; j; j >>= 1) { shfl_cmp_kv(x, xp, j, d, lane); shfl_cmp_kv(y, yp, j, d, lane); }
            }
            keys[64 * w + lane] = x;        pay[64 * w + lane] = xp;
            keys[64 * w + 32 + lane] = y;   pay[64 * w + 32 + lane] = yp;
        }
        __syncthreads();

        // cross-warp merge phases k=128,256; j<=32 fused into shfl segments
        #pragma unroll 1
        for (int k = 128; k <= MAXC; k <<= 1) {
            #pragma unroll 1
            for (int j = k >> 1; j >= 64; j >>= 1) {
                if (tid < MAXC / 2) {
                    int i = ((tid & ~(j - 1)) << 1) | (tid & (j - 1));
                    int p2 = i | j;
                    u64 a = keys[i], bb = keys[p2];
                    bool desc = ((i & k) == 0);
                    if (desc ? (a < bb) : (a > bb)) {
                        u32 ap = pay[i], bp = pay[p2];
                        keys[i] = bb; keys[p2] = a;
                        pay[i] = bp; pay[p2] = ap;
                    }
                }
                __syncthreads();
            }
            if (w < 4) {
                u64 xx = keys[64 * w + lane];        u32 xxp = pay[64 * w + lane];
                u64 yy = keys[64 * w + 32 + lane];   u32 yyp = pay[64 * w + 32 + lane];
                bool d = (((64 * w) & k) == 0);
                bool xmax = xx > yy;
                if (xmax != d) { u64 tk = xx; xx = yy; yy = tk; u32 tp = xxp; xxp = yyp; yyp = tp; }
                #pragma unroll
                for (int j = 16; j; j >>= 1) { shfl_cmp_kv(xx, xxp, j, d, lane); shfl_cmp_kv(yy, yyp, j, d, lane); }
                keys[64 * w + lane] = xx;        pay[64 * w + lane] = xxp;
                keys[64 * w + 32 + lane] = yy;   pay[64 * w + 32 + lane] = yyp;
            }
            __syncthreads();
        }

        // decode from smem records (keys dead; cor overlay safe, no extra barrier)
        if (tid < M) {
            u32 pa = pay[tid];
            float4 r0 = s_rec[2 * pa];
            float4 r1 = s_rec[2 * pa + 1];
            c_box[tid]   = r0;
            cor[tid]     = make_float4(r0.x - r0.z * 0.5f, r0.y - r0.w * 0.5f,
                                       r0.x + r0.z * 0.5f, r0.y + r0.w * 0.5f);
            c_score[tid] = r1.x;
            c_lab[tid]   = r1.y;
        }
        if (tid == 0) s_any = 0;
        __syncthreads();

        // fast IoU bit-matrix: Wlim==128 guaranteed; branchless + closing range mask
        {
            int rrr = tid >> 2, wi = tid & 3;
            int cbase = wi * 32;
            int lo = rrr - cbase;            // bits b<=lo are c<=rrr (to clear)
            u32 mask = 0;
            if (lo < 31) {
                float4 a = cor[rrr];
                float aar = (a.z - a.x) * (a.w - a.y);
                #pragma unroll 8
                for (int b = 0; b < 32; b++) {
                    float4 bb = cor[cbase + b];
                    float ti = fmaxf(a.x, bb.x), tj = fmaxf(a.y, bb.y);
                    float bi = fminf(a.z, bb.z), bj = fminf(a.w, bb.w);
                    float inter = fmaxf(bi - ti, 0.0f) * fmaxf(bj - tj, 0.0f);
                    float bar = (bb.z - bb.x) * (bb.w - bb.y);
                    float den = fmaxf(aar + bar - inter, 1e-12f);
                    if (inter > IOU_TH * den) mask |= (1u << b);
                }
                if (lo >= 0) mask &= ~((2u << lo) - 1u);
            }
            rowsw[rrr][wi] = mask;
            if (tid < 4) rowsw[NMSW][tid] = 0;
            if (mask) atomicOr(&s_any, 1u);  // rare
        }
        __syncthreads();

        if (s_any == 0) {
            if (tid < MAXDET) kept_rank[tid] = tid;
            if (tid == 0) s_nk = MAXDET;
        } else if (tid == 0) {
            const uint4* rv = (const uint4*)rowsw;
            u32 s0 = 0, s1 = 0, s2 = 0, s3 = 0;
            int nk = 0;
            uint4 rr = rv[0];
            for (int c = 0; c < NMSW && nk < MAXDET; ++c) {
                uint4 cur = rr;
                rr = rv[c + 1];
                u32 sw = (c < 64) ? ((c < 32) ? s0 : s1) : ((c < 96) ? s2 : s3);
                if (!((sw >> (c & 31)) & 1u)) {
                    kept_rank[nk++] = c;
                    s0 |= cur.x; s1 |= cur.y; s2 |= cur.z; s3 |= cur.w;
                }
            }
            s_nk = nk;
        }
        __syncthreads();

        if (s_nk < MAXDET) full = true;  // exactness post-check
    }

    // =================== FULL EXACT PATH (statistically never) ===================
    if (full) {
        if (tid == 0) s_fcnt = 0;
        for (int i = tid; i < CAP; i += NT) keys[i] = 0ull;
        __syncthreads();
        for (int n = tid; n < NANCH; n += NT) {
            float s = ibase[(size_t)n * NC + 5];
            if (s >= SCORE_TH) {
                int pos = atomicAdd(&s_fcnt, 1);
                if (pos < CAP) keys[pos] = pack_key(s, n);
            }
        }
        __syncthreads();
        M = min(min(s_fcnt, CAP), TOPK);
        for (int k = 2; k <= CAP; k <<= 1)
            for (int j = k >> 1; j; j >>= 1) {
                for (int t = tid; t < CAP / 2; t += NT) {
                    int i = ((t & ~(j - 1)) << 1) | (t & (j - 1));
                    int p = i | j;
                    u64 a = keys[i], bb = keys[p];
                    bool desc = ((i & k) == 0);
                    if (desc ? (a < bb) : (a > bb)) { keys[i] = bb; keys[p] = a; }
                }
                __syncthreads();
            }

        u64 ka = (tid < M)      ? keys[tid]      : 0ull;
        u64 kb = (tid + NT < M) ? keys[tid + NT] : 0ull;
        __syncthreads();
        #pragma unroll
        for (int half = 0; half < 2; ++half) {
            int i = tid + half * NT;
            u64 kk = half ? kb : ka;
            if (i < M) {
                int n = (int)(~(u32)kk);
                float score = __uint_as_float((u32)(kk >> 32) & 0x7fffffffu);
                int a = n % NA;
                int cell = n / NA;
                int gj = cell % GW;
                int gi = cell / GW;
                int si = a / 3, ri = a % 3;
                float s  = 0.5f * (float)(1 << si);
                float r  = 0.5f * (float)(1 << ri);
                float sr = sqrtf(r);
                float ah = (s * sr) * 0.03125f;
                float aw = (s / sr) * 0.03125f;
                float ci = ((float)gi + 0.5f) * (1.0f / 128.0f);
                float cj = ((float)gj + 0.5f) * (1.0f / 128.0f);
                const float* t = ibase + (size_t)n * NC;
                float di = ci + t[0] * ah;
                float dj = cj + t[1] * aw;
                float dh = ah * expf(t[2]);
                float dw = aw * expf(t[3]);
                c_box[i]   = make_float4(di, dj, dh, dw);
                cor[i]     = make_float4(di - dh * 0.5f, dj - dw * 0.5f,
                                         di + dh * 0.5f, dj + dw * 0.5f);
                c_score[i] = score;
                c_idx[i]   = n;
            }
        }
        if (tid == 0) s_any = 0;
        __syncthreads();

        const int Wlim = min(M, NMSW);
        {
            int rrr = tid >> 2, wi = tid & 3;
            u32 mask = 0;
            if (rrr < Wlim) {
                float4 a = cor[rrr];
                float aar = (a.z - a.x) * (a.w - a.y);
                int cbase = wi * 32;
                #pragma unroll 4
                for (int b = 0; b < 32; b++) {
                    int c = cbase + b;
                    if (c > rrr && c < Wlim) {
                        float4 bb = cor[c];
                        float ti = fmaxf(a.x, bb.x), tj = fmaxf(a.y, bb.y);
                        float bi = fminf(a.z, bb.z), bj = fminf(a.w, bb.w);
                        float inter = fmaxf(bi - ti, 0.0f) * fmaxf(bj - tj, 0.0f);
                        float bar = (bb.z - bb.x) * (bb.w - bb.y);
                        float den = fmaxf(aar + bar - inter, 1e-12f);
                        if (inter > IOU_TH * den) mask |= (1u << b);
                    }
                }
            }
            rowsw[rrr][wi] = mask;
            if (tid < 4) rowsw[NMSW][tid] = 0;
            if (mask) atomicOr(&s_any, 1u);
        }
        __syncthreads();

        if (s_any == 0) {
            int nk = min(Wlim, MAXDET);
            if (tid < nk) kept_rank[tid] = tid;
            if (tid == 0) s_nk = nk;
        } else if (tid == 0) {
            const uint4* rv = (const uint4*)rowsw;
            u32 s0 = 0, s1 = 0, s2 = 0, s3 = 0;
            int nk = 0;
            uint4 rr = rv[0];
            for (int c = 0; c < Wlim && nk < MAXDET; ++c) {
                uint4 cur = rr;
                rr = rv[c + 1];
                u32 sw = (c < 64) ? ((c < 32) ? s0 : s1) : ((c < 96) ? s2 : s3);
                if (!((sw >> (c & 31)) & 1u)) {
                    kept_rank[nk++] = c;
                    s0 |= cur.x; s1 |= cur.y; s2 |= cur.z; s3 |= cur.w;
                }
            }
            s_nk = nk;
        }
        __syncthreads();

        if (s_nk < MAXDET && M > Wlim) {
            if (tid < 32) {
                int nk = s_nk;
                float kc0[4], kc1[4], kc2[4], kc3[4], kar[4];
                #pragma unroll
                for (int sdx = 0; sdx < 4; ++sdx) {
                    int k = sdx * 32 + lane;
                    if (k < nk) {
                        float4 a = cor[kept_rank[k]];
                        kc0[sdx] = a.x; kc1[sdx] = a.y; kc2[sdx] = a.z; kc3[sdx] = a.w;
                        kar[sdx] = (a.z - a.x) * (a.w - a.y);
                    }
                }
                #pragma unroll 1
                for (int c = Wlim; c < M && nk < MAXDET; ++c) {
                    float4 a = cor[c];
                    float ar = (a.z - a.x) * (a.w - a.y);
                    bool pred = false;
                    #pragma unroll
                    for (int sdx = 0; sdx < 4; ++sdx) {
                        int k = sdx * 32 + lane;
                        if (k < nk) {
                            float ti = fmaxf(a.x, kc0[sdx]);
                            float tj = fmaxf(a.y, kc1[sdx]);
                            float bi = fminf(a.z, kc2[sdx]);
                            float bj = fminf(a.w, kc3[sdx]);
                            float inter = fmaxf(bi - ti, 0.0f) * fmaxf(bj - tj, 0.0f);
                            float den = fmaxf(kar[sdx] + ar - inter, 1e-12f);
                            pred |= inter > IOU_TH * den;
                        }
                    }
                    if (!__ballot_sync(0xffffffffu, pred)) {
                        int slot = nk >> 5, ln = nk & 31;
                        if (lane == ln) {
                            #pragma unroll
                            for (int sdx = 0; sdx < 4; ++sdx) {
                                if (slot == sdx) {
                                    kc0[sdx] = a.x; kc1[sdx] = a.y;
                                    kc2[sdx] = a.z; kc3[sdx] = a.w; kar[sdx] = ar;
                                }
                            }
                            kept_rank[nk] = c;
                        }
                        nk++;
                    }
                }
                if (lane == 0) s_nk = nk;
            }
            __syncthreads();
        }
    }

    // ---- epilogue ----
    const int nk = s_nk;
    if (!full) {
        if (tid < MAXDET) {
            float* o = out + (size_t)img * MAXDET * 6 + tid * 6;
            if (tid < nk) {
                int c = kept_rank[tid];
                float4 bx = c_box[c];
                o[0] = bx.x; o[1] = bx.y; o[2] = bx.z; o[3] = bx.w;
                o[4] = c_lab[c];
                o[5] = c_score[c];
            } else {
                o[0] = 0.0f; o[1] = 0.0f; o[2] = 0.0f;
                o[3] = 0.0f; o[4] = 0.0f; o[5] = 0.0f;
            }
        }
    } else {
        #pragma unroll 1
        for (int row = tid >> 3; row < MAXDET; row += NT / 8) {
            const int sub = tid & 7;
            float* o = out + (size_t)img * MAXDET * 6 + row * 6;
            const bool live = row < nk;
            int c = live ? kept_rank[row] : 0;
            int n = live ? c_idx[c] : 0;
            float bv = -1e38f; int bidx = 1 << 30;
            if (live) {
                const float* cls = ibase + (size_t)n * NC + 6;
                #pragma unroll
                for (int t = 0; t < 10; t++) {
                    int cc = sub + t * 8;
                    float v = __ldg(cls + cc);
                    if (v > bv) { bv = v; bidx = cc; }
                }
            }
            #pragma unroll
            for (int off = 4; off; off >>= 1) {
                float ov = __shfl_down_sync(0xffffffffu, bv, off, 8);
                int   oi = __shfl_down_sync(0xffffffffu, bidx, off, 8);
                if (ov > bv || (ov == bv && oi < bidx)) { bv = ov; bidx = oi; }
            }
            if (live) {
                if (sub == 0) {
                    float4 bx = c_box[c];
                    o[0] = bx.x; o[1] = bx.y; o[2] = bx.z; o[3] = bx.w;
                    o[4] = (float)bidx;
                    o[5] = c_score[c];
                }
            } else {
                if (sub < 6) o[sub] = 0.0f;
            }
        }
    }
}

extern "C" void kernel_launch(void* const* d_in, const int* in_sizes, int n_in,
                              void* d_out, int out_size) {
    (void)in_sizes; (void)n_in; (void)out_size;
    const float* in = (const float*)d_in[0];
    float* out = (float*)d_out;

    fused_kernel<<<NIMG * PCTA, NT>>>(in, out);
}